// round 5
// baseline (speedup 1.0000x reference)
#include <cuda_runtime.h>
#include <cstdint>

#define B_   16
#define N_   1024
#define M_   12
#define FB_  32
#define F_   128
#define ROWS_TOT (B_ * N_)   // 16384

__device__ float g_p[ROWS_TOT];
__device__ float g_s[ROWS_TOT];
__device__ float g_WT[F_ * F_];   // W transposed: g_WT[c*128 + k]

static __device__ __forceinline__ uint32_t s2u(const void* p) {
    return (uint32_t)__cvta_generic_to_shared(p);
}

// ---------------------------------------------------------------------------
// Kernel 1: p[b,n] = prod_m r_m / max(sum_m r_m,eps)^12,  r_m = 1/||bond||^2
// One warp per FOUR rows: 12 independent LDG.128 per thread (MLP).
// ---------------------------------------------------------------------------
__global__ void bond_kernel(const float* __restrict__ bond) {
    int warp = (blockIdx.x << 3) + (threadIdx.x >> 5);
    int lane = threadIdx.x & 31;
    int grp  = lane >> 3;          // m within quartet
    int sub  = lane & 7;           // float4 slot within FB=32
    int row0 = warp << 2;
    const float* b = bond + (size_t)row0 * (M_ * FB_);

    float4 v[4][3];
#pragma unroll
    for (int j = 0; j < 4; ++j)
#pragma unroll
        for (int i = 0; i < 3; ++i)
            v[j][i] = *(const float4*)(b + j * (M_ * FB_)
                                         + ((((i << 2) + grp) << 5) + (sub << 2)));

    float sum[4], prod[4];
#pragma unroll
    for (int j = 0; j < 4; ++j) { sum[j] = 0.f; prod[j] = 1.f; }

#pragma unroll
    for (int i = 0; i < 3; ++i) {
        float s[4];
#pragma unroll
        for (int j = 0; j < 4; ++j) {
            float4 u = v[j][i];
            s[j] = u.x*u.x + u.y*u.y + u.z*u.z + u.w*u.w;
        }
#pragma unroll
        for (int off = 1; off <= 4; off <<= 1)
#pragma unroll
            for (int j = 0; j < 4; ++j)
                s[j] += __shfl_xor_sync(0xffffffffu, s[j], off);
#pragma unroll
        for (int j = 0; j < 4; ++j) {
            float r = 1.0f / s[j];     // (sqrt(s))^-2 == 1/s
            sum[j] += r; prod[j] *= r;
        }
    }
#pragma unroll
    for (int off = 8; off <= 16; off <<= 1)
#pragma unroll
        for (int j = 0; j < 4; ++j) {
            sum[j]  += __shfl_xor_sync(0xffffffffu, sum[j], off);
            prod[j] *= __shfl_xor_sync(0xffffffffu, prod[j], off);
        }
    if (lane < 4) {
        float S = (lane == 0) ? sum[0]  : (lane == 1) ? sum[1]  : (lane == 2) ? sum[2]  : sum[3];
        float P = (lane == 0) ? prod[0] : (lane == 1) ? prod[1] : (lane == 2) ? prod[2] : prod[3];
        float D = fmaxf(S, 1e-12f);
        float d2 = D * D, d4 = d2 * d2;
        g_p[row0 + lane] = P / (d4 * d4 * d4);
    }
}

// ---------------------------------------------------------------------------
// Kernel 2: blocks 0..15: s[b,n]; blocks 16,17: transpose W into g_WT.
// ---------------------------------------------------------------------------
__global__ void s_kernel(const float* __restrict__ W) {
    if (blockIdx.x >= B_) {
        int base = (blockIdx.x - B_) * 8192 + threadIdx.x;
#pragma unroll
        for (int i = 0; i < 8; ++i) {
            int idx = base + (i << 10);                 // k*128 + c
            g_WT[(idx & 127) * F_ + (idx >> 7)] = W[idx];
        }
        return;
    }
    __shared__ float red[32];
    int b = blockIdx.x, n = threadIdx.x;
    int wid = n >> 5, lane = n & 31;

    float cs = 0.f;
#pragma unroll
    for (int bb = 0; bb < B_; ++bb) cs += g_p[bb * N_ + n];
    float u = fmaxf(cs, 1e-12f) / g_p[b * N_ + n];

    float v = u;
#pragma unroll
    for (int off = 16; off; off >>= 1) v += __shfl_xor_sync(0xffffffffu, v, off);
    if (lane == 0) red[wid] = v;
    __syncthreads();
    if (wid == 0) {
        float t = red[lane];
#pragma unroll
        for (int off = 16; off; off >>= 1) t += __shfl_xor_sync(0xffffffffu, t, off);
        if (lane == 0) red[0] = 1.0f / fmaxf(t, 1e-12f);
    }
    __syncthreads();
    g_s[b * N_ + n] = u * red[0];
}

// ---------------------------------------------------------------------------
// Kernel 3: fused gather + mean + scale + GEMM + bias + ReLU
//   Block: 256 threads, 64 rows x 128 cols, microtile 8 rows x 4 cols.
//   K-packed fma.rn.f32x2 (hi/lo k-partials), W staged transposed+swizzled.
//   Single __syncthreads. Dynamic smem: sA 32KB + sWT 64KB = 96KB.
// ---------------------------------------------------------------------------
extern __shared__ float dsm[];

__global__ __launch_bounds__(256, 2) void fused_kernel(
    const float* __restrict__ atom, const int* __restrict__ adj,
    const float* __restrict__ bias, float* __restrict__ out)
{
    float (*sA)[F_] = (float(*)[F_])dsm;            // [64][128]
    float4* sWT     = (float4*)(dsm + 64 * F_);     // [128 c][32 kq] swizzled

    int tid  = threadIdx.x;
    int wid  = tid >> 5;
    int lane = tid & 31;
    int row0 = blockIdx.x << 6;

    // ---- Stage W (transposed) with swizzle: phys_f4 = c*32 + (kq ^ (c&7)) ----
    {
        const float4* src = (const float4*)g_WT;
#pragma unroll
        for (int t = 0; t < 16; ++t) {
            int q  = tid + (t << 8);
            int c  = q >> 5, kq = q & 31;
            sWT[(c << 5) + (kq ^ (c & 7))] = src[q];
        }
    }

    // ---- Build A tile: each warp produces 8 rows ----
#pragma unroll
    for (int rr = 0; rr < 8; ++rr) {
        int r = (wid << 3) + rr;
        int g = row0 + r;
        int b = g >> 10;
        const float* arow  = atom + ((size_t)g << 7);
        const float* abase = atom + ((size_t)b << 17);
        int myidx = (lane < M_) ? adj[(size_t)g * M_ + lane] : 0;

        float4 self = *(const float4*)(arow + (lane << 2));
        float ax = 0.f, ay = 0.f, az = 0.f, aw = 0.f;
#pragma unroll
        for (int m = 0; m < M_; ++m) {
            int idx = __shfl_sync(0xffffffffu, myidx, m) & (N_ - 1);
            float4 nb = *(const float4*)(abase + ((size_t)idx << 7) + (lane << 2));
            ax += nb.x; ay += nb.y; az += nb.z; aw += nb.w;
        }
        float sc = g_s[g];
        const float inv12 = 1.0f / 12.0f;
        float4 av;
        av.x = (self.x + ax * inv12) * sc;
        av.y = (self.y + ay * inv12) * sc;
        av.z = (self.z + az * inv12) * sc;
        av.w = (self.w + aw * inv12) * sc;
        *(float4*)&sA[r][lane << 2] = av;
    }
    __syncthreads();

    // ---- Mainloop: 32 k-quads, k-packed f32x2 ----
    uint64_t acc[8][4];
#pragma unroll
    for (int r = 0; r < 8; ++r)
#pragma unroll
        for (int i = 0; i < 4; ++i) acc[r][i] = 0ull;

    uint32_t a_base = s2u(dsm) + ((wid << 3) * F_) * 4;       // row wid*8, bytes
    uint32_t w_mem  = s2u(dsm + 64 * F_);
    uint32_t sw16   = (uint32_t)(lane & 7) << 4;
    uint32_t wb0 = w_mem + (uint32_t)(lane)      * 512;
    uint32_t wb1 = w_mem + (uint32_t)(lane + 32) * 512;
    uint32_t wb2 = w_mem + (uint32_t)(lane + 64) * 512;
    uint32_t wb3 = w_mem + (uint32_t)(lane + 96) * 512;

#pragma unroll 4
    for (int kq = 0; kq < 32; ++kq) {
        uint32_t koff = (uint32_t)kq << 4;
        uint32_t woff = koff ^ sw16;
        uint64_t w0l, w0h, w1l, w1h, w2l, w2h, w3l, w3h;
        asm("ld.shared.v2.u64 {%0,%1}, [%2];" : "=l"(w0l), "=l"(w0h) : "r"(wb0 + woff));
        asm("ld.shared.v2.u64 {%0,%1}, [%2];" : "=l"(w1l), "=l"(w1h) : "r"(wb1 + woff));
        asm("ld.shared.v2.u64 {%0,%1}, [%2];" : "=l"(w2l), "=l"(w2h) : "r"(wb2 + woff));
        asm("ld.shared.v2.u64 {%0,%1}, [%2];" : "=l"(w3l), "=l"(w3h) : "r"(wb3 + woff));
#pragma unroll
        for (int r = 0; r < 8; ++r) {
            uint64_t al, ah;
            asm("ld.shared.v2.u64 {%0,%1}, [%2];"
                : "=l"(al), "=l"(ah) : "r"(a_base + (uint32_t)(r * F_ * 4) + koff));
            asm("fma.rn.f32x2 %0, %1, %2, %0;" : "+l"(acc[r][0]) : "l"(al), "l"(w0l));
            asm("fma.rn.f32x2 %0, %1, %2, %0;" : "+l"(acc[r][1]) : "l"(al), "l"(w1l));
            asm("fma.rn.f32x2 %0, %1, %2, %0;" : "+l"(acc[r][2]) : "l"(al), "l"(w2l));
            asm("fma.rn.f32x2 %0, %1, %2, %0;" : "+l"(acc[r][3]) : "l"(al), "l"(w3l));
            asm("fma.rn.f32x2 %0, %1, %2, %0;" : "+l"(acc[r][0]) : "l"(ah), "l"(w0h));
            asm("fma.rn.f32x2 %0, %1, %2, %0;" : "+l"(acc[r][1]) : "l"(ah), "l"(w1h));
            asm("fma.rn.f32x2 %0, %1, %2, %0;" : "+l"(acc[r][2]) : "l"(ah), "l"(w2h));
            asm("fma.rn.f32x2 %0, %1, %2, %0;" : "+l"(acc[r][3]) : "l"(ah), "l"(w3h));
        }
    }

    // ---- Epilogue: combine hi+lo partials, bias + ReLU, scalar coalesced ----
    float bv[4];
#pragma unroll
    for (int i = 0; i < 4; ++i) bv[i] = bias[lane + (i << 5)];

#pragma unroll
    for (int r = 0; r < 8; ++r) {
        int g = row0 + (wid << 3) + r;
        float* orow = out + ((size_t)g << 7);
#pragma unroll
        for (int i = 0; i < 4; ++i) {
            float lo, hi;
            asm("mov.b64 {%0, %1}, %2;" : "=f"(lo), "=f"(hi) : "l"(acc[r][i]));
            orow[lane + (i << 5)] = fmaxf(lo + hi + bv[i], 0.f);
        }
    }
}

// ---------------------------------------------------------------------------
extern "C" void kernel_launch(void* const* d_in, const int* in_sizes, int n_in,
                              void* d_out, int out_size) {
    const float* atom = (const float*)d_in[0];
    const float* bond = (const float*)d_in[1];
    const int*   adj  = (const int*)d_in[2];
    const float* W    = (const float*)d_in[3];
    const float* bias = (const float*)d_in[4];
    float*       out  = (float*)d_out;

    static bool attr_done = false;
    if (!attr_done) {
        cudaFuncSetAttribute(fused_kernel,
                             cudaFuncAttributeMaxDynamicSharedMemorySize, 98304);
        attr_done = true;
    }

    bond_kernel <<<ROWS_TOT / 32, 256>>>(bond);
    s_kernel    <<<B_ + 2, 1024>>>(W);
    fused_kernel<<<ROWS_TOT / 64, 256, 98304>>>(atom, adj, bias, out);
}